// round 8
// baseline (speedup 1.0000x reference)
#include <cuda_runtime.h>
#include <cuda_fp16.h>
#include <cstdint>

#define NI 16384
#define IPB 64
#define NTHREADS 256
#define NBLK (NI / IPB)

// gemm kernel smem: X[64m][128k]f16 16KB @0; H[64m][256k]f16 32KB @0 (reuse)
#define XHO  0u
#define HHO  0u
#define META 32768u
#define SMEM_BYTES 36864

__device__ uint4 g_w1f[4096];                       // W1 mma-B fragment image
__device__ uint4 g_w2f[2048];                       // W2 mma-B fragment image
__device__ __align__(16) unsigned char g_x[NI * 256]; // X rows, fp16 [16384][128]

static __device__ __forceinline__ uint32_t smem_u32(const void* p) {
    uint32_t a;
    asm("{ .reg .u64 t; cvta.to.shared.u64 t, %1; cvt.u32.u64 %0, t; }" : "=r"(a) : "l"(p));
    return a;
}
static __device__ __forceinline__ uint64_t gmem_u64(const void* p) {
    uint64_t a;
    asm("cvta.to.global.u64 %0, %1;" : "=l"(a) : "l"(p));
    return a;
}
static __device__ __forceinline__ uint32_t xoff(int m, int k) {   // 256B rows
    return (uint32_t)(m * 256 + ((k * 2) ^ ((m & 7) * 16)));
}
static __device__ __forceinline__ uint32_t hoff(int m, int k) {   // 512B rows
    return (uint32_t)(m * 512 + ((k * 2) ^ ((m & 7) * 16)));
}
static __device__ __forceinline__ uint32_t h2u(__half2 v) {
    return *reinterpret_cast<uint32_t*>(&v);
}
static __device__ __forceinline__ void st_h2(char* sm, uint32_t o, float a, float b) {
    *(uint32_t*)(sm + o) = h2u(__floats2half2_rn(a, b));
}
static __device__ __forceinline__ uint2 pack_h4(float4 v) {
    return make_uint2(h2u(__floats2half2_rn(v.x, v.y)), h2u(__floats2half2_rn(v.z, v.w)));
}
static __device__ __forceinline__ void cp16(uint32_t dst, uint64_t src) {
    asm volatile("cp.async.cg.shared.global [%0], [%1], 16;" :: "r"(dst), "l"(src) : "memory");
}
#define CP_COMMIT() asm volatile("cp.async.commit_group;" ::: "memory")
#define CP_WAIT0()  asm volatile("cp.async.wait_group 0;" ::: "memory")

static __device__ __forceinline__ void ldm_x4(uint32_t* r, uint32_t a) {
    asm volatile("ldmatrix.sync.aligned.m8n8.x4.shared.b16 {%0,%1,%2,%3}, [%4];"
        : "=r"(r[0]), "=r"(r[1]), "=r"(r[2]), "=r"(r[3]) : "r"(a));
}
static __device__ __forceinline__ void mma16816h(float* c, const uint32_t* a, const uint32_t* b) {
    asm volatile("mma.sync.aligned.m16n8k16.row.col.f32.f16.f16.f32 "
        "{%0,%1,%2,%3}, {%4,%5,%6,%7}, {%8,%9}, {%0,%1,%2,%3};"
        : "+f"(c[0]), "+f"(c[1]), "+f"(c[2]), "+f"(c[3])
        : "r"(a[0]), "r"(a[1]), "r"(a[2]), "r"(a[3]), "r"(b[0]), "r"(b[1]));
}

// ---- prologue: fragment-ordered fp16 weight images ----
__global__ __launch_bounds__(256)
void make_frags(const float* __restrict__ W1, const float* __restrict__ W2) {
    const int t = blockIdx.x * blockDim.x + threadIdx.x;
    if (t < 4096) {
        const int kt = t >> 9, rem = t & 511;
        const int p = rem >> 5, lane = rem & 31;
        const int k0 = kt * 16 + (lane & 3) * 2;
        const int nA = p * 16 + (lane >> 2), nB = nA + 8;
        uint4 v;
        v.x = h2u(__floats2half2_rn(W1[(size_t)k0 * 256 + nA], W1[(size_t)(k0 + 1) * 256 + nA]));
        v.y = h2u(__floats2half2_rn(W1[(size_t)(k0 + 8) * 256 + nA], W1[(size_t)(k0 + 9) * 256 + nA]));
        v.z = h2u(__floats2half2_rn(W1[(size_t)k0 * 256 + nB], W1[(size_t)(k0 + 1) * 256 + nB]));
        v.w = h2u(__floats2half2_rn(W1[(size_t)(k0 + 8) * 256 + nB], W1[(size_t)(k0 + 9) * 256 + nB]));
        g_w1f[t] = v;
    } else if (t < 6144) {
        const int u = t - 4096;
        const int kt = u >> 7, rem = u & 127;
        const int p = rem >> 5, lane = rem & 31;
        const int k0 = kt * 16 + (lane & 3) * 2;
        const int nA = p * 16 + (lane >> 2), nB = nA + 8;
        uint4 v;
        v.x = h2u(__floats2half2_rn(W2[(size_t)k0 * 64 + nA], W2[(size_t)(k0 + 1) * 64 + nA]));
        v.y = h2u(__floats2half2_rn(W2[(size_t)(k0 + 8) * 64 + nA], W2[(size_t)(k0 + 9) * 64 + nA]));
        v.z = h2u(__floats2half2_rn(W2[(size_t)k0 * 64 + nB], W2[(size_t)(k0 + 1) * 64 + nB]));
        v.w = h2u(__floats2half2_rn(W2[(size_t)(k0 + 8) * 64 + nB], W2[(size_t)(k0 + 9) * 64 + nB]));
        g_w2f[u] = v;
    }
}

// ---- kernel A: pure streaming gather (no smem, no barriers) ----
__global__ __launch_bounds__(256)
void gather_kernel(const int* __restrict__ item_ids,
                   const int* __restrict__ tag_ids,
                   const int* __restrict__ tag_lens,
                   const float* __restrict__ item_table,
                   const float* __restrict__ dat_table,
                   const float* __restrict__ tag_table,
                   float* __restrict__ out)
{
    const int t = blockIdx.x * 256 + threadIdx.x;   // 0 .. 262143
    const int i = t >> 4, d4 = t & 15;

    const int id  = __ldg(item_ids + i);
    const int len = __ldg(tag_lens + i);
    const int4 tg0 = __ldg((const int4*)(tag_ids + (size_t)i * 8));
    const int4 tg1 = __ldg((const int4*)(tag_ids + (size_t)i * 8) + 1);
    const int tg[8] = {tg0.x, tg0.y, tg0.z, tg0.w, tg1.x, tg1.y, tg1.z, tg1.w};

    const float4 ei = __ldg((const float4*)(item_table + (size_t)id * 64) + d4);
    const float4 ed = __ldg((const float4*)(dat_table + (size_t)id * 64) + d4);

    const float4 z4 = make_float4(0.f, 0.f, 0.f, 0.f);
    float4 tv[8];
    #pragma unroll
    for (int j = 0; j < 8; j++)
        tv[j] = (j < len) ? __ldg((const float4*)(tag_table + (size_t)tg[j] * 64) + d4) : z4;

    float4 sum = make_float4(0.f, 0.f, 0.f, 0.f);
    #pragma unroll
    for (int j = 0; j < 8; j++) {
        sum.x += tv[j].x; sum.y += tv[j].y; sum.z += tv[j].z; sum.w += tv[j].w;
    }
    const float inv = 1.0f / (float)len;

    // e_dat -> out tail (coalesced)
    ((float4*)(out + (size_t)NI * 64 + (size_t)i * 64))[d4] = ed;
    // X row: item part at bytes [8*d4], tag-mean part at [128 + 8*d4]
    uint2* xrow = (uint2*)(g_x + (size_t)i * 256);
    xrow[d4] = pack_h4(ei);
    xrow[16 + d4] = pack_h4(make_float4(sum.x * inv, sum.y * inv, sum.z * inv, sum.w * inv));
}

// ---- kernel B: all-tensor tower ----
__global__ __launch_bounds__(NTHREADS, 2)
void gemm_tower(const float* __restrict__ b1,
                const float* __restrict__ b2,
                float* __restrict__ out)
{
    extern __shared__ __align__(128) char sm[];
    const uint32_t smb = smem_u32(sm);
    const int tid = threadIdx.x;
    const int lane = tid & 31;
    const int wid = tid >> 5;
    const int gi0 = blockIdx.x * IPB;

    float* b1s = (float*)(sm + META);          // [256]
    float* b2s = (float*)(sm + META + 1024);   // [64]

    // ---- DMA X tile into swizzled smem ----
    {
        const uint64_t src = gmem_u64(g_x) + (size_t)gi0 * 256;
        #pragma unroll
        for (int j = 0; j < 4; j++) {
            const int c = tid + j * NTHREADS;          // 1024 chunks of 16B
            const int m = c >> 4, c16 = c & 15;
            cp16(smb + XHO + (uint32_t)(m * 256 + ((c16 * 16) ^ ((m & 7) * 16))),
                 src + c * 16);
        }
        CP_COMMIT();
    }
    b1s[tid] = b1[tid];
    if (tid < 64) b2s[tid] = b2[tid];
    CP_WAIT0();
    __syncthreads();

    // ---- GEMM1: C[64,256] = X @ W1 (B frags from L2) ----
    const int wm = wid >> 2, wn = wid & 3;        // 2x4 warp grid
    const int m0 = wm * 32, n0g = wn * 64;
    float acc[2][8][4];
    #pragma unroll
    for (int a = 0; a < 2; a++)
        #pragma unroll
        for (int j = 0; j < 8; j++)
            #pragma unroll
            for (int q = 0; q < 4; q++) acc[a][j][q] = 0.f;

    #pragma unroll
    for (int kt = 0; kt < 8; kt++) {
        const int k0 = kt * 16;
        uint32_t B[8][2];
        #pragma unroll
        for (int np = 0; np < 4; np++) {
            const uint4 v = __ldg(g_w1f + ((kt * 16 + wn * 4 + np) * 32 + lane));
            B[np * 2][0] = v.x; B[np * 2][1] = v.y;
            B[np * 2 + 1][0] = v.z; B[np * 2 + 1][1] = v.w;
        }
        uint32_t A[2][4];
        #pragma unroll
        for (int mt = 0; mt < 2; mt++) {
            const int r = m0 + mt * 16 + (lane & 15);
            ldm_x4(A[mt], smb + XHO + xoff(r, k0 + ((lane >> 4) << 3)));
        }
        #pragma unroll
        for (int mt = 0; mt < 2; mt++)
            #pragma unroll
            for (int nt = 0; nt < 8; nt++)
                mma16816h(acc[mt][nt], A[mt], B[nt]);
    }
    __syncthreads();

    // ---- H = relu(C + b1) -> fp16 smem ----
    #pragma unroll
    for (int mt = 0; mt < 2; mt++)
        #pragma unroll
        for (int nt = 0; nt < 8; nt++) {
            const int ncol = n0g + nt * 8 + 2 * (lane & 3);
            const float2 bias = *(const float2*)(b1s + ncol);
            const float* c = acc[mt][nt];
            const int r = m0 + mt * 16 + (lane >> 2);
            st_h2(sm, HHO + hoff(r, ncol),
                  fmaxf(c[0] + bias.x, 0.f), fmaxf(c[1] + bias.y, 0.f));
            st_h2(sm, HHO + hoff(r + 8, ncol),
                  fmaxf(c[2] + bias.x, 0.f), fmaxf(c[3] + bias.y, 0.f));
        }
    __syncthreads();

    // ---- GEMM2: O[64,64] = H @ W2 ----
    const int m0b = (wid >> 1) * 16;              // 4x2 warp grid
    const int wc = wid & 1;
    const int n0b = wc * 32;
    float acc2[4][4];
    #pragma unroll
    for (int j = 0; j < 4; j++)
        #pragma unroll
        for (int q = 0; q < 4; q++) acc2[j][q] = 0.f;

    #pragma unroll
    for (int kt = 0; kt < 16; kt++) {
        const int k0 = kt * 16;
        uint32_t B[4][2];
        #pragma unroll
        for (int np = 0; np < 2; np++) {
            const uint4 v = __ldg(g_w2f + ((kt * 4 + wc * 2 + np) * 32 + lane));
            B[np * 2][0] = v.x; B[np * 2][1] = v.y;
            B[np * 2 + 1][0] = v.z; B[np * 2 + 1][1] = v.w;
        }
        uint32_t A[4];
        {
            const int r = m0b + (lane & 15);
            ldm_x4(A, smb + HHO + hoff(r, k0 + ((lane >> 4) << 3)));
        }
        #pragma unroll
        for (int nt = 0; nt < 4; nt++)
            mma16816h(acc2[nt], A, B[nt]);
    }

    // ---- epilogue: out = O + b2 ----
    #pragma unroll
    for (int nt = 0; nt < 4; nt++) {
        const int n = n0b + nt * 8 + 2 * (lane & 3);
        const float2 bias = *(const float2*)(b2s + n);
        const int r = gi0 + m0b + (lane >> 2);
        *(float2*)(out + (size_t)r * 64 + n) =
            make_float2(acc2[nt][0] + bias.x, acc2[nt][1] + bias.y);
        *(float2*)(out + (size_t)(r + 8) * 64 + n) =
            make_float2(acc2[nt][2] + bias.x, acc2[nt][3] + bias.y);
    }
}

extern "C" void kernel_launch(void* const* d_in, const int* in_sizes, int n_in,
                              void* d_out, int out_size) {
    cudaFuncSetAttribute(gemm_tower,
                         cudaFuncAttributeMaxDynamicSharedMemorySize, SMEM_BYTES);
    make_frags<<<24, 256>>>((const float*)d_in[6], (const float*)d_in[8]);
    gather_kernel<<<NI * 16 / 256, 256>>>(
        (const int*)d_in[0], (const int*)d_in[1], (const int*)d_in[2],
        (const float*)d_in[3], (const float*)d_in[4], (const float*)d_in[5],
        (float*)d_out);
    gemm_tower<<<NBLK, NTHREADS, SMEM_BYTES>>>(
        (const float*)d_in[7], (const float*)d_in[9], (float*)d_out);
}

// round 9
// speedup vs baseline: 1.1165x; 1.1165x over previous
#include <cuda_runtime.h>
#include <cuda_fp16.h>
#include <cstdint>

#define NI 16384
#define IPB 64
#define NTHREADS 256
#define NBLK (NI / IPB)

// gemm kernel smem: X[64m][128k]f16 16KB @0; H[64m][256k]f16 32KB @0 (reuse)
#define XHO  0u
#define HHO  0u
#define META 32768u
#define SMEM_BYTES 36864

__device__ uint4 g_w1f[4096];                         // W1 mma-B fragment image
__device__ uint4 g_w2f[2048];                         // W2 mma-B fragment image
__device__ __align__(16) unsigned char g_x[NI * 256]; // X rows, fp16 [16384][128]

static __device__ __forceinline__ uint32_t smem_u32(const void* p) {
    uint32_t a;
    asm("{ .reg .u64 t; cvta.to.shared.u64 t, %1; cvt.u32.u64 %0, t; }" : "=r"(a) : "l"(p));
    return a;
}
static __device__ __forceinline__ uint64_t gmem_u64(const void* p) {
    uint64_t a;
    asm("cvta.to.global.u64 %0, %1;" : "=l"(a) : "l"(p));
    return a;
}
static __device__ __forceinline__ uint32_t xoff(int m, int k) {   // 256B rows
    return (uint32_t)(m * 256 + ((k * 2) ^ ((m & 7) * 16)));
}
static __device__ __forceinline__ uint32_t hoff(int m, int k) {   // 512B rows
    return (uint32_t)(m * 512 + ((k * 2) ^ ((m & 7) * 16)));
}
static __device__ __forceinline__ uint32_t h2u(__half2 v) {
    return *reinterpret_cast<uint32_t*>(&v);
}
static __device__ __forceinline__ void st_h2(char* sm, uint32_t o, float a, float b) {
    *(uint32_t*)(sm + o) = h2u(__floats2half2_rn(a, b));
}
static __device__ __forceinline__ uint2 pack_h4(float4 v) {
    return make_uint2(h2u(__floats2half2_rn(v.x, v.y)), h2u(__floats2half2_rn(v.z, v.w)));
}
static __device__ __forceinline__ void cp16(uint32_t dst, uint64_t src) {
    asm volatile("cp.async.cg.shared.global [%0], [%1], 16;" :: "r"(dst), "l"(src) : "memory");
}
#define CP_COMMIT() asm volatile("cp.async.commit_group;" ::: "memory")
#define CP_WAIT0()  asm volatile("cp.async.wait_group 0;" ::: "memory")

static __device__ __forceinline__ void ldm_x4(uint32_t* r, uint32_t a) {
    asm volatile("ldmatrix.sync.aligned.m8n8.x4.shared.b16 {%0,%1,%2,%3}, [%4];"
        : "=r"(r[0]), "=r"(r[1]), "=r"(r[2]), "=r"(r[3]) : "r"(a));
}
static __device__ __forceinline__ void mma16816h(float* c, const uint32_t* a, const uint32_t* b) {
    asm volatile("mma.sync.aligned.m16n8k16.row.col.f32.f16.f16.f32 "
        "{%0,%1,%2,%3}, {%4,%5,%6,%7}, {%8,%9}, {%0,%1,%2,%3};"
        : "+f"(c[0]), "+f"(c[1]), "+f"(c[2]), "+f"(c[3])
        : "r"(a[0]), "r"(a[1]), "r"(a[2]), "r"(a[3]), "r"(b[0]), "r"(b[1]));
}

// ---- kernel A: streaming gather + (blocks 0..23) weight frag build ----
__global__ __launch_bounds__(256)
void gather_kernel(const int* __restrict__ item_ids,
                   const int* __restrict__ tag_ids,
                   const int* __restrict__ tag_lens,
                   const float* __restrict__ item_table,
                   const float* __restrict__ dat_table,
                   const float* __restrict__ tag_table,
                   const float* __restrict__ W1,
                   const float* __restrict__ W2,
                   float* __restrict__ out)
{
    const int t = blockIdx.x * 256 + threadIdx.x;   // 0 .. 262143

    // -- frag build (first 6144 threads; gemm kernel consumes after this kernel ends) --
    if (t < 6144) {
        if (t < 4096) {
            const int kt = t >> 9, rem = t & 511;
            const int p = rem >> 5, lane = rem & 31;
            const int k0 = kt * 16 + (lane & 3) * 2;
            const int nA = p * 16 + (lane >> 2), nB = nA + 8;
            uint4 v;
            v.x = h2u(__floats2half2_rn(W1[(size_t)k0 * 256 + nA], W1[(size_t)(k0 + 1) * 256 + nA]));
            v.y = h2u(__floats2half2_rn(W1[(size_t)(k0 + 8) * 256 + nA], W1[(size_t)(k0 + 9) * 256 + nA]));
            v.z = h2u(__floats2half2_rn(W1[(size_t)k0 * 256 + nB], W1[(size_t)(k0 + 1) * 256 + nB]));
            v.w = h2u(__floats2half2_rn(W1[(size_t)(k0 + 8) * 256 + nB], W1[(size_t)(k0 + 9) * 256 + nB]));
            g_w1f[t] = v;
        } else {
            const int u = t - 4096;
            const int kt = u >> 7, rem = u & 127;
            const int p = rem >> 5, lane = rem & 31;
            const int k0 = kt * 16 + (lane & 3) * 2;
            const int nA = p * 16 + (lane >> 2), nB = nA + 8;
            uint4 v;
            v.x = h2u(__floats2half2_rn(W2[(size_t)k0 * 64 + nA], W2[(size_t)(k0 + 1) * 64 + nA]));
            v.y = h2u(__floats2half2_rn(W2[(size_t)(k0 + 8) * 64 + nA], W2[(size_t)(k0 + 9) * 64 + nA]));
            v.z = h2u(__floats2half2_rn(W2[(size_t)k0 * 64 + nB], W2[(size_t)(k0 + 1) * 64 + nB]));
            v.w = h2u(__floats2half2_rn(W2[(size_t)(k0 + 8) * 64 + nB], W2[(size_t)(k0 + 9) * 64 + nB]));
            g_w2f[u] = v;
        }
    }

    // -- gather --
    const int i = t >> 4, d4 = t & 15;
    const int id  = __ldg(item_ids + i);
    const int len = __ldg(tag_lens + i);
    const int4 tg0 = __ldg((const int4*)(tag_ids + (size_t)i * 8));
    const int4 tg1 = __ldg((const int4*)(tag_ids + (size_t)i * 8) + 1);
    const int tg[8] = {tg0.x, tg0.y, tg0.z, tg0.w, tg1.x, tg1.y, tg1.z, tg1.w};

    const float4 ei = __ldg((const float4*)(item_table + (size_t)id * 64) + d4);
    const float4 ed = __ldg((const float4*)(dat_table + (size_t)id * 64) + d4);

    const float4 z4 = make_float4(0.f, 0.f, 0.f, 0.f);
    float4 tv[8];
    #pragma unroll
    for (int j = 0; j < 8; j++)
        tv[j] = (j < len) ? __ldg((const float4*)(tag_table + (size_t)tg[j] * 64) + d4) : z4;

    float4 sum = make_float4(0.f, 0.f, 0.f, 0.f);
    #pragma unroll
    for (int j = 0; j < 8; j++) {
        sum.x += tv[j].x; sum.y += tv[j].y; sum.z += tv[j].z; sum.w += tv[j].w;
    }
    const float inv = 1.0f / (float)len;

    // e_dat -> out tail (coalesced)
    ((float4*)(out + (size_t)NI * 64 + (size_t)i * 64))[d4] = ed;
    // X row: item part bytes [8*d4], tag-mean part [128 + 8*d4]
    uint2* xrow = (uint2*)(g_x + (size_t)i * 256);
    xrow[d4] = pack_h4(ei);
    xrow[16 + d4] = pack_h4(make_float4(sum.x * inv, sum.y * inv, sum.z * inv, sum.w * inv));
}

// ---- kernel B: all-tensor tower ----
__global__ __launch_bounds__(NTHREADS, 2)
void gemm_tower(const float* __restrict__ b1,
                const float* __restrict__ b2,
                float* __restrict__ out)
{
    extern __shared__ __align__(128) char sm[];
    const uint32_t smb = smem_u32(sm);
    const int tid = threadIdx.x;
    const int lane = tid & 31;
    const int wid = tid >> 5;
    const int gi0 = blockIdx.x * IPB;

    float* b1s = (float*)(sm + META);          // [256]
    float* b2s = (float*)(sm + META + 1024);   // [64]

    // ---- DMA X tile into swizzled smem ----
    {
        const uint64_t src = gmem_u64(g_x) + (size_t)gi0 * 256;
        #pragma unroll
        for (int j = 0; j < 4; j++) {
            const int c = tid + j * NTHREADS;          // 1024 chunks of 16B
            const int m = c >> 4, c16 = c & 15;
            cp16(smb + XHO + (uint32_t)(m * 256 + ((c16 * 16) ^ ((m & 7) * 16))),
                 src + c * 16);
        }
        CP_COMMIT();
    }
    b1s[tid] = b1[tid];
    if (tid < 64) b2s[tid] = b2[tid];
    CP_WAIT0();
    __syncthreads();

    // ---- GEMM1: C[64,256] = X @ W1 (B frags from L2) ----
    const int wm = wid >> 2, wn = wid & 3;        // 2x4 warp grid
    const int m0 = wm * 32, n0g = wn * 64;
    float acc[2][8][4];
    #pragma unroll
    for (int a = 0; a < 2; a++)
        #pragma unroll
        for (int j = 0; j < 8; j++)
            #pragma unroll
            for (int q = 0; q < 4; q++) acc[a][j][q] = 0.f;

    #pragma unroll
    for (int kt = 0; kt < 8; kt++) {
        const int k0 = kt * 16;
        uint32_t B[8][2];
        #pragma unroll
        for (int np = 0; np < 4; np++) {
            const uint4 v = __ldg(g_w1f + ((kt * 16 + wn * 4 + np) * 32 + lane));
            B[np * 2][0] = v.x; B[np * 2][1] = v.y;
            B[np * 2 + 1][0] = v.z; B[np * 2 + 1][1] = v.w;
        }
        uint32_t A[2][4];
        #pragma unroll
        for (int mt = 0; mt < 2; mt++) {
            const int r = m0 + mt * 16 + (lane & 15);
            ldm_x4(A[mt], smb + XHO + xoff(r, k0 + ((lane >> 4) << 3)));
        }
        #pragma unroll
        for (int mt = 0; mt < 2; mt++)
            #pragma unroll
            for (int nt = 0; nt < 8; nt++)
                mma16816h(acc[mt][nt], A[mt], B[nt]);
    }
    __syncthreads();

    // ---- H = relu(C + b1) -> fp16 smem ----
    #pragma unroll
    for (int mt = 0; mt < 2; mt++)
        #pragma unroll
        for (int nt = 0; nt < 8; nt++) {
            const int ncol = n0g + nt * 8 + 2 * (lane & 3);
            const float2 bias = *(const float2*)(b1s + ncol);
            const float* c = acc[mt][nt];
            const int r = m0 + mt * 16 + (lane >> 2);
            st_h2(sm, HHO + hoff(r, ncol),
                  fmaxf(c[0] + bias.x, 0.f), fmaxf(c[1] + bias.y, 0.f));
            st_h2(sm, HHO + hoff(r + 8, ncol),
                  fmaxf(c[2] + bias.x, 0.f), fmaxf(c[3] + bias.y, 0.f));
        }
    __syncthreads();

    // ---- GEMM2: O[64,64] = H @ W2 ----
    const int m0b = (wid >> 1) * 16;              // 4x2 warp grid
    const int wc = wid & 1;
    const int n0b = wc * 32;
    float acc2[4][4];
    #pragma unroll
    for (int j = 0; j < 4; j++)
        #pragma unroll
        for (int q = 0; q < 4; q++) acc2[j][q] = 0.f;

    #pragma unroll
    for (int kt = 0; kt < 16; kt++) {
        const int k0 = kt * 16;
        uint32_t B[4][2];
        #pragma unroll
        for (int np = 0; np < 2; np++) {
            const uint4 v = __ldg(g_w2f + ((kt * 4 + wc * 2 + np) * 32 + lane));
            B[np * 2][0] = v.x; B[np * 2][1] = v.y;
            B[np * 2 + 1][0] = v.z; B[np * 2 + 1][1] = v.w;
        }
        uint32_t A[4];
        {
            const int r = m0b + (lane & 15);
            ldm_x4(A, smb + HHO + hoff(r, k0 + ((lane >> 4) << 3)));
        }
        #pragma unroll
        for (int nt = 0; nt < 4; nt++)
            mma16816h(acc2[nt], A, B[nt]);
    }

    // ---- epilogue: out = O + b2 ----
    #pragma unroll
    for (int nt = 0; nt < 4; nt++) {
        const int n = n0b + nt * 8 + 2 * (lane & 3);
        const float2 bias = *(const float2*)(b2s + n);
        const int r = gi0 + m0b + (lane >> 2);
        *(float2*)(out + (size_t)r * 64 + n) =
            make_float2(acc2[nt][0] + bias.x, acc2[nt][1] + bias.y);
        *(float2*)(out + (size_t)(r + 8) * 64 + n) =
            make_float2(acc2[nt][2] + bias.x, acc2[nt][3] + bias.y);
    }
}

extern "C" void kernel_launch(void* const* d_in, const int* in_sizes, int n_in,
                              void* d_out, int out_size) {
    cudaFuncSetAttribute(gemm_tower,
                         cudaFuncAttributeMaxDynamicSharedMemorySize, SMEM_BYTES);
    gather_kernel<<<NI * 16 / 256, 256>>>(
        (const int*)d_in[0], (const int*)d_in[1], (const int*)d_in[2],
        (const float*)d_in[3], (const float*)d_in[4], (const float*)d_in[5],
        (const float*)d_in[6], (const float*)d_in[8],
        (float*)d_out);
    gemm_tower<<<NBLK, NTHREADS, SMEM_BYTES>>>(
        (const float*)d_in[7], (const float*)d_in[9], (float*)d_out);
}